// round 16
// baseline (speedup 1.0000x reference)
#include <cuda_runtime.h>
#include <math.h>

// ---------------- problem constants ----------------
#define BB    64
#define NIN   1024
#define NHID  1024
#define NOUT  10
#define TSN   500          // time bins
#define KS    77           // SRM kernel taps (truncated alpha kernel, tau=10)
#define KR    11           // refractory kernel taps (tau=1), REF[0]==0
#define THETA 10.0f
#define TT    20           // timesteps per spmm block
#define NTG   (TSN / TT)   // 25
#define TCAP  384          // per-t event list capacity (mean 51, sigma 7)

// ---------------- scratch (static device memory; no allocations) ----------------
__device__ float g_srm[KS];
__device__ float g_refk[KR];
__device__ float g_w1t[(size_t)(NIN + 1) * NHID];        // W1^T [i][o]; row NIN is all-zero (pad row)
__device__ float g_z1[(size_t)BB * NHID * TSN];          // 131 MB (z, then u in-place)
__device__ unsigned char g_s1[(size_t)BB * NHID * TSN];  // 33 MB (binary spikes as u8)
__device__ float g_z2[(size_t)BB * NOUT * TSN];          // 1.28 MB (z2, then u2 in-place)

// packed f32x2 FMA: two independent IEEE fp32 FMAs, bit-exact vs scalar FFMA
__device__ __forceinline__ unsigned long long ffma2(unsigned long long a,
                                                    unsigned long long b,
                                                    unsigned long long c) {
    unsigned long long d;
    asm("fma.rn.f32x2 %0, %1, %2, %3;" : "=l"(d) : "l"(a), "l"(b), "l"(c));
    return d;
}

// ---------------- kernel tap init (double, matches python math.exp -> f32) ----------------
__global__ void init_kernel() {
    int i = threadIdx.x;
    if (i < KS) {
        double t = (double)i;
        g_srm[i] = (float)(t / 10.0 * exp(1.0 - t / 10.0));
    }
    if (i < KR) {
        double t = (double)i;
        g_refk[i] = (float)(-20.0 * t * exp(1.0 - t));   // mult = -2*theta, tau_ref = 1
    }
    // zero pad row of W1^T (used by event-list padding)
    for (int k = threadIdx.x; k < NHID; k += blockDim.x)
        g_w1t[(size_t)NIN * NHID + k] = 0.0f;
}

// ---------------- W1 transpose: g_w1t[i][o] = W1[o][i] ----------------
__global__ void transpose_kernel(const float* __restrict__ w1) {
    __shared__ float tile[32][33];
    int i0 = blockIdx.x * 32;
    int o0 = blockIdx.y * 32;
    for (int j = threadIdx.y; j < 32; j += 8)
        tile[j][threadIdx.x] = w1[(size_t)(o0 + j) * NIN + i0 + threadIdx.x];
    __syncthreads();
    for (int j = threadIdx.y; j < 32; j += 8)
        g_w1t[(size_t)(i0 + j) * NHID + o0 + threadIdx.x] = tile[threadIdx.x][j];
}

// ---------------- layer-1 GEMM via per-timestep event lists ----------------
// block = (b, t-group of TT=20); 512 threads, each owns 2 output rows (o2, o2+1).
// For each t: z1[b,o,t0+t] = sum over active i ASCENDING of W1[o,i]  (order-exact).
__global__ __launch_bounds__(512, 3) void spmm1_kernel(const float* __restrict__ x) {
    __shared__ unsigned msk[NIN];
    __shared__ unsigned short tl[TT][TCAP];
    __shared__ int tcnt[TT];
    __shared__ float wb[10][513];

    int b  = blockIdx.y;
    int t0 = blockIdx.x * TT;
    const float* xb = x + (size_t)b * NIN * TSN + t0;

    // phase 1: per-input activity bitmask over TT timesteps (float4 loads, 16B aligned)
    for (int i = threadIdx.x; i < NIN; i += 512) {
        const float4* xr = (const float4*)(xb + (size_t)i * TSN);
        unsigned m = 0;
#pragma unroll
        for (int j4 = 0; j4 < TT / 4; ++j4) {
            float4 v = xr[j4];
            if (v.x != 0.0f) m |= 1u << (j4 * 4 + 0);
            if (v.y != 0.0f) m |= 1u << (j4 * 4 + 1);
            if (v.z != 0.0f) m |= 1u << (j4 * 4 + 2);
            if (v.w != 0.0f) m |= 1u << (j4 * 4 + 3);
        }
        msk[i] = m;
    }
    __syncthreads();

    // phase 2: build 20 per-t event lists in parallel (warp w -> t = w, w+16)
    {
        int wid  = threadIdx.x >> 5;
        int lane = threadIdx.x & 31;
        for (int t = wid; t < TT; t += 16) {
            int base = 0;
            for (int c = 0; c < NIN / 32; ++c) {
                int i = c * 32 + lane;
                bool a = (msk[i] >> t) & 1u;
                unsigned bal = __ballot_sync(0xffffffffu, a);
                if (a) {
                    int pos = base + __popc(bal & ((1u << lane) - 1u));
                    if (pos < TCAP - 12) tl[t][pos] = (unsigned short)i;
                }
                base += __popc(bal);
            }
            if (base > TCAP - 12) base = TCAP - 12;
            if (lane < 12) tl[t][base + lane] = (unsigned short)NIN;   // zero-row pads
            if (lane == 0) tcnt[t] = (base + 3) & ~3;
        }
    }
    __syncthreads();

    int o2 = threadIdx.x * 2;
    const float* wbase = g_w1t + o2;

#define LW(I) (*(const float2*)(wbase + (size_t)(I) * NHID))

    // two passes of 10 timesteps each (keeps hot accumulator a small)
#pragma unroll
    for (int p = 0; p < 2; ++p) {
        float2 A[10];
#pragma unroll
        for (int tt = 0; tt < 10; ++tt) {
            int t = p * 10 + tt;
            const unsigned short* lt = tl[t];
            int n = tcnt[t];
            float2 a = make_float2(0.f, 0.f);
            ushort4 I = *(const ushort4*)&lt[0];
            float2 w0 = LW(I.x), w1 = LW(I.y), w2 = LW(I.z), w3 = LW(I.w);
            for (int e = 0; e < n; e += 4) {
                ushort4 I2 = *(const ushort4*)&lt[e + 4];
                float2 p0 = LW(I2.x), p1 = LW(I2.y);
                a.x += w0.x; a.y += w0.y;
                a.x += w1.x; a.y += w1.y;
                float2 p2 = LW(I2.z), p3 = LW(I2.w);
                a.x += w2.x; a.y += w2.y;
                a.x += w3.x; a.y += w3.y;
                w0 = p0; w1 = p1; w2 = p2; w3 = p3;
            }
            A[tt] = a;
        }

        // staged coalesced writes: two halves of 512 outputs
#pragma unroll 1
        for (int h = 0; h < 2; ++h) {
            __syncthreads();
            if ((int)(threadIdx.x >> 8) == h) {
                int ol = (threadIdx.x & 255) * 2;
#pragma unroll
                for (int j = 0; j < 10; ++j) { wb[j][ol] = A[j].x; wb[j][ol + 1] = A[j].y; }
            }
            __syncthreads();
            int obase = b * NHID + h * 512;
            for (int idx = threadIdx.x; idx < 512 * 10; idx += 512) {
                int oo = idx / 10, j = idx - oo * 10;
                g_z1[(size_t)(obase + oo) * TSN + t0 + p * 10 + j] = wb[j][oo];
            }
        }
    }
#undef LW
}

// ---------------- row-paired t-parallel 77-tap FIR via packed f32x2, in-place ----------------
// Each 64-thread group handles a PAIR of rows (2p, 2p+1); window staged interleaved
// {rowA,rowB} so one LDS.64 feeds an FFMA2 doing both rows. Per tap per thread:
// 8 FFMA2 (16 MACs) + 1 LDS.64 window + 1 LDS.64 broadcast tap.
// smem deinterleaved by 8: lane l reads pair wi=8l+c -> sub-array c, offset 8l bytes
// -> banks (2l, 2l+1) per half-warp phase: conflict-free.
#define NPG 4               // row-pairs per block (256 threads)
#define WQ8 74
__global__ __launch_bounds__(256) void conv_kernel(float* __restrict__ buf) {
    __shared__ float2 srm2[KS];
    __shared__ float2 phys[NPG][8][WQ8];

    int tid = threadIdx.x;
    int g = tid >> 6;           // row-pair within block, 0..3
    int l = tid & 63;           // 0..63

    for (int k = tid; k < KS; k += 256) {
        float w = g_srm[k];
        srm2[k] = make_float2(w, w);
    }

    size_t pr = (size_t)blockIdx.x * NPG + g;
    float* rowA = buf + (pr * 2)     * TSN;
    float* rowB = buf + (pr * 2 + 1) * TSN;

    // stage window pairs: win[wi] = z[wi-76] for wi in [76,576), else 0; wi in [0,584)
    for (int wi = l; wi < 584; wi += 64) {
        float a = 0.0f, bv = 0.0f;
        if (wi >= 76 && wi < 576) { a = rowA[wi - 76]; bv = rowB[wi - 76]; }
        phys[g][wi & 7][wi >> 3] = make_float2(a, bv);
    }
    __syncthreads();

#define P(WI) (*(const unsigned long long*)&phys[g][(WI) & 7][(WI) >> 3])
    bool active = (l < 63);
    int tb = active ? l * 8 : 0;      // output base t, 0..496
    unsigned long long U[8];
#pragma unroll
    for (int j = 0; j < 8; ++j) U[j] = 0ULL;
    if (active) {
        unsigned long long v[8];
#pragma unroll
        for (int j = 0; j < 8; ++j) v[j] = P(tb + 76 + j);
#pragma unroll
        for (int k = 0; k < KS; ++k) {
            unsigned long long wp = *(const unsigned long long*)&srm2[k];  // broadcast
#pragma unroll
            for (int j = 0; j < 8; ++j) U[j] = ffma2(wp, v[j], U[j]);
            if (k + 1 < KS) {
#pragma unroll
                for (int j = 7; j > 0; --j) v[j] = v[j - 1];
                v[0] = P(tb + 75 - k);
            }
        }
    }
    __syncthreads();   // single, block-wide: all reads done before in-place overwrite
    if (active) {
        float uA[8], uB[8];
#pragma unroll
        for (int j = 0; j < 8; ++j) {
            union { unsigned long long u; float2 f; } c;
            c.u = U[j];
            uA[j] = c.f.x; uB[j] = c.f.y;
        }
        *(float4*)(rowA + tb) = make_float4(uA[0], uA[1], uA[2], uA[3]);
        *(float4*)(rowB + tb) = make_float4(uB[0], uB[1], uB[2], uB[3]);
        if (tb + 7 < TSN) {
            *(float4*)(rowA + tb + 4) = make_float4(uA[4], uA[5], uA[6], uA[7]);
            *(float4*)(rowB + tb + 4) = make_float4(uB[4], uB[5], uB[6], uB[7]);
        }
    }
#undef P
}

// ---------------- LIF scan (refractory feedback), one thread per row; u8 spike out ----------------
#define LIF_STEP(UIN, SOUT)                                             \
    {                                                                   \
        float u_ = (UIN) + rb[0];                                       \
        float s_ = (u_ >= THETA) ? 1.0f : 0.0f;                         \
        _Pragma("unroll")                                               \
        for (int j_ = 0; j_ < 9; ++j_) rb[j_] = rb[j_ + 1] + s_ * rk[j_ + 1]; \
        rb[9] = s_ * rk[10];                                            \
        (SOUT) = s_;                                                    \
    }

__global__ __launch_bounds__(256) void scan1_kernel() {
    float rk[KR];
#pragma unroll
    for (int j = 0; j < KR; ++j) rk[j] = g_refk[j];

    size_t r = (size_t)blockIdx.x * blockDim.x + threadIdx.x;   // 0..65535
    const float4* u  = (const float4*)(g_z1 + r * TSN);
    uchar4*      sp = (uchar4*)(g_s1 + r * TSN);

    float rb[10];
#pragma unroll
    for (int j = 0; j < 10; ++j) rb[j] = 0.0f;

    for (int c = 0; c < TSN / 4; ++c) {
        float4 uu = u[c];
        float s0, s1v, s2v, s3;
        LIF_STEP(uu.x, s0);
        LIF_STEP(uu.y, s1v);
        LIF_STEP(uu.z, s2v);
        LIF_STEP(uu.w, s3);
        uchar4 so;
        so.x = (unsigned char)s0;
        so.y = (unsigned char)s1v;
        so.z = (unsigned char)s2v;
        so.w = (unsigned char)s3;
        sp[c] = so;
    }
}

// ---------------- layer-2 GEMM with smem-tiled s1 (u8): z2[b,o,t] = sum_i W2[o,i]*s1[b,i,t] ----------------
// i processed in 4 chunks of 256, each staged once to smem -> 10 o-warps read smem,
// not L2, cutting the 10x reread. Chunk order + within-chunk i ascending = order-exact.
__global__ __launch_bounds__(320) void dense2_kernel(const float* __restrict__ w2) {
    __shared__ float ws[NOUT * NHID];
    __shared__ uchar4 tile[256][32];

    int lt = threadIdx.y * 32 + threadIdx.x;
    for (int k = lt; k < NOUT * NHID; k += 320) ws[k] = w2[k];

    int q = blockIdx.x * 32 + threadIdx.x;  // uchar4 index along t, 0..127 (125 valid)
    int o = threadIdx.y;
    int b = blockIdx.y;
    bool qok = (q < TSN / 4);

    const uchar4* s1b = ((const uchar4*)(g_s1 + (size_t)b * NHID * TSN));
    const float*  wr  = ws + o * NHID;

    float4 acc = make_float4(0.f, 0.f, 0.f, 0.f);

#pragma unroll 1
    for (int c = 0; c < 4; ++c) {
        __syncthreads();
        // stage chunk [c*256, c*256+256) x block's 32 q
        for (int idx = lt; idx < 256 * 32; idx += 320) {
            int il = idx >> 5, qq = idx & 31;
            int qg = blockIdx.x * 32 + qq;
            if (qg < TSN / 4)
                tile[il][qq] = s1b[(size_t)(c * 256 + il) * (TSN / 4) + qg];
        }
        __syncthreads();
        if (qok) {
#pragma unroll 8
            for (int il = 0; il < 256; ++il) {
                float w = wr[c * 256 + il];
                uchar4 s = tile[il][threadIdx.x];
                acc.x += w * (float)s.x;
                acc.y += w * (float)s.y;
                acc.z += w * (float)s.z;
                acc.w += w * (float)s.w;
            }
        }
    }
    if (qok) {
        float4* zo = ((float4*)(g_z2 + ((size_t)(b * NOUT + o)) * TSN)) + q;
        *zo = acc;
    }
}

// ---------------- layer-2 LIF scan -> final output (reads u in-place from g_z2) ----------------
__global__ void scan2_kernel(float* __restrict__ out) {
    float rk[KR];
#pragma unroll
    for (int j = 0; j < KR; ++j) rk[j] = g_refk[j];

    int r = blockIdx.x * blockDim.x + threadIdx.x;
    if (r >= BB * NOUT) return;
    const float4* u = (const float4*)(g_z2 + (size_t)r * TSN);
    float4* o = (float4*)(out + (size_t)r * TSN);

    float rb[10];
#pragma unroll
    for (int j = 0; j < 10; ++j) rb[j] = 0.0f;

    for (int c = 0; c < TSN / 4; ++c) {
        float4 uu = u[c];
        float4 so;
        LIF_STEP(uu.x, so.x);
        LIF_STEP(uu.y, so.y);
        LIF_STEP(uu.z, so.z);
        LIF_STEP(uu.w, so.w);
        o[c] = so;
    }
}

// ---------------- launcher ----------------
extern "C" void kernel_launch(void* const* d_in, const int* in_sizes, int n_in,
                              void* d_out, int out_size) {
    const float* x  = (const float*)d_in[0];   // spike_input [64,1024,500]
    const float* w1 = (const float*)d_in[1];   // W1 [1024,1024]
    const float* w2 = (const float*)d_in[2];   // W2 [10,1024]
    float* out = (float*)d_out;                // s2 [64,10,500]

    float* z1p; cudaGetSymbolAddress((void**)&z1p, g_z1);
    float* z2p; cudaGetSymbolAddress((void**)&z2p, g_z2);

    init_kernel<<<1, 128>>>();                              // launch 1
    transpose_kernel<<<dim3(32, 32), dim3(32, 8)>>>(w1);    // launch 2
    spmm1_kernel<<<dim3(NTG, BB), 512>>>(x);                // launch 3
    conv_kernel<<<BB * NHID / (2 * NPG), 256>>>(z1p);       // launch 4 <- ncu capture
    scan1_kernel<<<BB * NHID / 256, 256>>>();               // launch 5
    dense2_kernel<<<dim3(4, BB), dim3(32, 10)>>>(w2);       // launch 6
    conv_kernel<<<BB * NOUT / (2 * NPG), 256>>>(z2p);       // launch 7
    scan2_kernel<<<(BB * NOUT + 255) / 256, 256>>>(out);    // launch 8
}

// round 17
// speedup vs baseline: 1.3773x; 1.3773x over previous
#include <cuda_runtime.h>
#include <math.h>

// ---------------- problem constants ----------------
#define BB    64
#define NIN   1024
#define NHID  1024
#define NOUT  10
#define TSN   500          // time bins
#define KS    77           // SRM kernel taps (truncated alpha kernel, tau=10)
#define KR    11           // refractory kernel taps (tau=1), REF[0]==0
#define THETA 10.0f
#define TT    20           // timesteps per spmm block
#define NTG   (TSN / TT)   // 25
#define TCAP  384          // per-t event list capacity (mean 51, sigma 7)

// ---------------- scratch (static device memory; no allocations) ----------------
__device__ float g_srm[KS];
__device__ float g_refk[KR];
__device__ float g_w1t[(size_t)(NIN + 1) * NHID];        // W1^T [i][o]; row NIN is all-zero (pad row)
__device__ float g_z1[(size_t)BB * NHID * TSN];          // 131 MB (z, then u in-place)
__device__ unsigned char g_s1[(size_t)BB * NHID * TSN];  // 33 MB (binary spikes as u8)
__device__ float g_z2[(size_t)BB * NOUT * TSN];          // 1.28 MB (z2, then u2 in-place)

// ---------------- kernel tap init (double, matches python math.exp -> f32) ----------------
__global__ void init_kernel() {
    int i = threadIdx.x;
    if (i < KS) {
        double t = (double)i;
        g_srm[i] = (float)(t / 10.0 * exp(1.0 - t / 10.0));
    }
    if (i < KR) {
        double t = (double)i;
        g_refk[i] = (float)(-20.0 * t * exp(1.0 - t));   // mult = -2*theta, tau_ref = 1
    }
    // zero pad row of W1^T (used by event-list padding)
    for (int k = threadIdx.x; k < NHID; k += blockDim.x)
        g_w1t[(size_t)NIN * NHID + k] = 0.0f;
}

// ---------------- W1 transpose: g_w1t[i][o] = W1[o][i] ----------------
__global__ void transpose_kernel(const float* __restrict__ w1) {
    __shared__ float tile[32][33];
    int i0 = blockIdx.x * 32;
    int o0 = blockIdx.y * 32;
    for (int j = threadIdx.y; j < 32; j += 8)
        tile[j][threadIdx.x] = w1[(size_t)(o0 + j) * NIN + i0 + threadIdx.x];
    __syncthreads();
    for (int j = threadIdx.y; j < 32; j += 8)
        g_w1t[(size_t)(i0 + j) * NHID + o0 + threadIdx.x] = tile[threadIdx.x][j];
}

// ---------------- layer-1 GEMM via per-timestep event lists ----------------
// block = (b, t-group of TT=20); 512 threads, each owns 2 output rows (o2, o2+1).
// For each t: z1[b,o,t0+t] = sum over active i ASCENDING of W1[o,i]  (order-exact).
// Branchless inner loop: ushort4 index fetch -> 4 x LDG.64 -> 8 FADD, 4-deep prefetch.
// Lists padded with index NIN (all-zero W row): +0.0f adds are exact no-ops.
__global__ __launch_bounds__(512, 3) void spmm1_kernel(const float* __restrict__ x) {
    __shared__ unsigned msk[NIN];
    __shared__ unsigned short tl[TT][TCAP];
    __shared__ int tcnt[TT];
    __shared__ float wb[10][513];

    int b  = blockIdx.y;
    int t0 = blockIdx.x * TT;
    const float* xb = x + (size_t)b * NIN * TSN + t0;

    // phase 1: per-input activity bitmask over TT timesteps (float4 loads, 16B aligned)
    for (int i = threadIdx.x; i < NIN; i += 512) {
        const float4* xr = (const float4*)(xb + (size_t)i * TSN);
        unsigned m = 0;
#pragma unroll
        for (int j4 = 0; j4 < TT / 4; ++j4) {
            float4 v = xr[j4];
            if (v.x != 0.0f) m |= 1u << (j4 * 4 + 0);
            if (v.y != 0.0f) m |= 1u << (j4 * 4 + 1);
            if (v.z != 0.0f) m |= 1u << (j4 * 4 + 2);
            if (v.w != 0.0f) m |= 1u << (j4 * 4 + 3);
        }
        msk[i] = m;
    }
    __syncthreads();

    // phase 2: build 20 per-t event lists in parallel (warp w -> t = w, w+16)
    {
        int wid  = threadIdx.x >> 5;
        int lane = threadIdx.x & 31;
        for (int t = wid; t < TT; t += 16) {
            int base = 0;
            for (int c = 0; c < NIN / 32; ++c) {
                int i = c * 32 + lane;
                bool a = (msk[i] >> t) & 1u;
                unsigned bal = __ballot_sync(0xffffffffu, a);
                if (a) {
                    int pos = base + __popc(bal & ((1u << lane) - 1u));
                    if (pos < TCAP - 12) tl[t][pos] = (unsigned short)i;
                }
                base += __popc(bal);
            }
            if (base > TCAP - 12) base = TCAP - 12;
            if (lane < 12) tl[t][base + lane] = (unsigned short)NIN;   // zero-row pads
            if (lane == 0) tcnt[t] = (base + 3) & ~3;
        }
    }
    __syncthreads();

    int o2 = threadIdx.x * 2;
    const float* wbase = g_w1t + o2;

#define LW(I) (*(const float2*)(wbase + (size_t)(I) * NHID))

    // two passes of 10 timesteps each (keeps hot accumulator a small)
#pragma unroll
    for (int p = 0; p < 2; ++p) {
        float2 A[10];
#pragma unroll
        for (int tt = 0; tt < 10; ++tt) {
            int t = p * 10 + tt;
            const unsigned short* lt = tl[t];
            int n = tcnt[t];
            float2 a = make_float2(0.f, 0.f);
            ushort4 I = *(const ushort4*)&lt[0];
            float2 w0 = LW(I.x), w1 = LW(I.y), w2 = LW(I.z), w3 = LW(I.w);
            for (int e = 0; e < n; e += 4) {
                ushort4 I2 = *(const ushort4*)&lt[e + 4];
                float2 p0 = LW(I2.x), p1 = LW(I2.y);
                a.x += w0.x; a.y += w0.y;
                a.x += w1.x; a.y += w1.y;
                float2 p2 = LW(I2.z), p3 = LW(I2.w);
                a.x += w2.x; a.y += w2.y;
                a.x += w3.x; a.y += w3.y;
                w0 = p0; w1 = p1; w2 = p2; w3 = p3;
            }
            A[tt] = a;
        }

        // staged coalesced writes: two halves of 512 outputs
#pragma unroll 1
        for (int h = 0; h < 2; ++h) {
            __syncthreads();
            if ((int)(threadIdx.x >> 8) == h) {
                int ol = (threadIdx.x & 255) * 2;
#pragma unroll
                for (int j = 0; j < 10; ++j) { wb[j][ol] = A[j].x; wb[j][ol + 1] = A[j].y; }
            }
            __syncthreads();
            int obase = b * NHID + h * 512;
            for (int idx = threadIdx.x; idx < 512 * 10; idx += 512) {
                int oo = idx / 10, j = idx - oo * 10;
                g_z1[(size_t)(obase + oo) * TSN + t0 + p * 10 + j] = wb[j][oo];
            }
        }
    }
#undef LW
}

// ---------------- generic t-parallel 77-tap causal FIR, u written in-place ----------------
// 4 rows/block, 64 threads/row, 8 outputs/thread: per tap 1 LDS + 8 FFMA.
// This sits AT the scalar-FFMA issue floor (~148us for layer 1) — measured R12.
// smem deinterleaved by 8 (phys[r][wi&7][wi>>3]) so the stride-8 window reads are
// conflict-free. Used for layer-1 (g_z1, 65536 rows) AND layer-2 (g_z2, 640 rows).
#define NR  4
#define WQ8 74
__global__ __launch_bounds__(256) void conv_kernel(float* __restrict__ buf) {
    __shared__ float srm_s[KS];
    __shared__ float phys[NR][8][WQ8];

    int tid = threadIdx.x;
    int r = tid >> 6;           // row within block, 0..3
    int l = tid & 63;           // 0..63

    for (int k = tid; k < KS; k += 256) srm_s[k] = g_srm[k];

    size_t row = (size_t)blockIdx.x * NR + r;
    float* zrow = buf + row * TSN;

    // stage window: win[wi] = z[wi-76] for wi in [76,576), else 0; wi in [0,584)
    for (int wi = l; wi < 584; wi += 64) {
        float v = (wi >= 76 && wi < 576) ? zrow[wi - 76] : 0.0f;
        phys[r][wi & 7][wi >> 3] = v;
    }
    __syncthreads();

#define S(WI) phys[r][(WI) & 7][(WI) >> 3]
    bool active = (l < 63);
    int tb = active ? l * 8 : 0;      // output base t, 0..496
    float u[8] = {0.f, 0.f, 0.f, 0.f, 0.f, 0.f, 0.f, 0.f};
    if (active) {
        float v[8];
#pragma unroll
        for (int j = 0; j < 8; ++j) v[j] = S(tb + 76 + j);
#pragma unroll
        for (int k = 0; k < KS; ++k) {
            float w = srm_s[k];
#pragma unroll
            for (int j = 0; j < 8; ++j) u[j] += w * v[j];
            if (k + 1 < KS) {
#pragma unroll
                for (int j = 7; j > 0; --j) v[j] = v[j - 1];
                v[0] = S(tb + 75 - k);
            }
        }
    }
    __syncthreads();   // single, block-wide: all reads done before in-place overwrite
    if (active) {
        *(float4*)(zrow + tb)     = make_float4(u[0], u[1], u[2], u[3]);
        if (tb + 7 < TSN)
            *(float4*)(zrow + tb + 4) = make_float4(u[4], u[5], u[6], u[7]);
    }
#undef S
}

// ---------------- LIF scan (refractory feedback), one thread per row; u8 spike out ----------------
#define LIF_STEP(UIN, SOUT)                                             \
    {                                                                   \
        float u_ = (UIN) + rb[0];                                       \
        float s_ = (u_ >= THETA) ? 1.0f : 0.0f;                         \
        _Pragma("unroll")                                               \
        for (int j_ = 0; j_ < 9; ++j_) rb[j_] = rb[j_ + 1] + s_ * rk[j_ + 1]; \
        rb[9] = s_ * rk[10];                                            \
        (SOUT) = s_;                                                    \
    }

__global__ __launch_bounds__(256) void scan1_kernel() {
    float rk[KR];
#pragma unroll
    for (int j = 0; j < KR; ++j) rk[j] = g_refk[j];

    size_t r = (size_t)blockIdx.x * blockDim.x + threadIdx.x;   // 0..65535
    const float4* u  = (const float4*)(g_z1 + r * TSN);
    uchar4*      sp = (uchar4*)(g_s1 + r * TSN);

    float rb[10];
#pragma unroll
    for (int j = 0; j < 10; ++j) rb[j] = 0.0f;

    // unroll 5 (125 % 5 == 0): batches the scan-independent u[c] loads -> MLP 5
#pragma unroll 5
    for (int c = 0; c < TSN / 4; ++c) {
        float4 uu = u[c];
        float s0, s1v, s2v, s3;
        LIF_STEP(uu.x, s0);
        LIF_STEP(uu.y, s1v);
        LIF_STEP(uu.z, s2v);
        LIF_STEP(uu.w, s3);
        uchar4 so;
        so.x = (unsigned char)s0;
        so.y = (unsigned char)s1v;
        so.z = (unsigned char)s2v;
        so.w = (unsigned char)s3;
        sp[c] = so;
    }
}

// ---------------- layer-2 GEMM: z2[b,o,t] = sum_i W2[o,i] * s1[b,i,t] (s1 is u8 0/1) ----------------
__global__ __launch_bounds__(320) void dense2_kernel(const float* __restrict__ w2) {
    __shared__ float ws[NOUT * NHID];
    int lt = threadIdx.y * 32 + threadIdx.x;
    for (int k = lt; k < NOUT * NHID; k += 320) ws[k] = w2[k];
    __syncthreads();

    int q = blockIdx.x * 32 + threadIdx.x;  // uchar4 index along t, 0..124
    if (q >= TSN / 4) return;
    int o = threadIdx.y;
    int b = blockIdx.y;

    const uchar4* s1b = ((const uchar4*)(g_s1 + (size_t)b * NHID * TSN)) + q;
    const float*  wr  = ws + o * NHID;

    float4 acc = make_float4(0.f, 0.f, 0.f, 0.f);
#pragma unroll 8
    for (int i = 0; i < NHID; ++i) {
        float w = wr[i];
        uchar4 s = s1b[(size_t)i * (TSN / 4)];
        acc.x += w * (float)s.x;
        acc.y += w * (float)s.y;
        acc.z += w * (float)s.z;
        acc.w += w * (float)s.w;
    }
    float4* zo = ((float4*)(g_z2 + ((size_t)(b * NOUT + o)) * TSN)) + q;
    *zo = acc;
}

// ---------------- layer-2 LIF scan -> final output (reads u in-place from g_z2) ----------------
__global__ void scan2_kernel(float* __restrict__ out) {
    float rk[KR];
#pragma unroll
    for (int j = 0; j < KR; ++j) rk[j] = g_refk[j];

    int r = blockIdx.x * blockDim.x + threadIdx.x;
    if (r >= BB * NOUT) return;
    const float4* u = (const float4*)(g_z2 + (size_t)r * TSN);
    float4* o = (float4*)(out + (size_t)r * TSN);

    float rb[10];
#pragma unroll
    for (int j = 0; j < 10; ++j) rb[j] = 0.0f;

#pragma unroll 5
    for (int c = 0; c < TSN / 4; ++c) {
        float4 uu = u[c];
        float4 so;
        LIF_STEP(uu.x, so.x);
        LIF_STEP(uu.y, so.y);
        LIF_STEP(uu.z, so.z);
        LIF_STEP(uu.w, so.w);
        o[c] = so;
    }
}

// ---------------- launcher ----------------
extern "C" void kernel_launch(void* const* d_in, const int* in_sizes, int n_in,
                              void* d_out, int out_size) {
    const float* x  = (const float*)d_in[0];   // spike_input [64,1024,500]
    const float* w1 = (const float*)d_in[1];   // W1 [1024,1024]
    const float* w2 = (const float*)d_in[2];   // W2 [10,1024]
    float* out = (float*)d_out;                // s2 [64,10,500]

    float* z1p; cudaGetSymbolAddress((void**)&z1p, g_z1);
    float* z2p; cudaGetSymbolAddress((void**)&z2p, g_z2);

    init_kernel<<<1, 128>>>();                              // launch 1
    transpose_kernel<<<dim3(32, 32), dim3(32, 8)>>>(w1);    // launch 2
    spmm1_kernel<<<dim3(NTG, BB), 512>>>(x);                // launch 3
    conv_kernel<<<BB * NHID / NR, 256>>>(z1p);              // launch 4 <- ncu capture
    scan1_kernel<<<BB * NHID / 256, 256>>>();               // launch 5
    dense2_kernel<<<dim3(4, BB), dim3(32, 10)>>>(w2);       // launch 6
    conv_kernel<<<BB * NOUT / NR, 256>>>(z2p);              // launch 7
    scan2_kernel<<<(BB * NOUT + 255) / 256, 256>>>(out);    // launch 8
}